// round 10
// baseline (speedup 1.0000x reference)
#include <cuda_runtime.h>
#include <cuda_fp16.h>
#include <math.h>
#include <float.h>
#include <stdint.h>

#define BATCH 4
#define SEQ   2048
#define DM    1024
#define ROWS  (BATCH * SEQ)   // 8192

#define BM 128
#define BN 256
#define BK 32                 // halves per K-slice
#define LDH 40                // halves per smem row (80B; LDSM conflict-free)
#define THREADS 256
#define STAGES 3
#define MAT_A_BYTES (BM * LDH * 2)           // 10240
#define MAT_B_BYTES (BN * LDH * 2)           // 20480
#define STG_BYTES (MAT_A_BYTES + MAT_B_BYTES) // 30720
#define SMEM_BYTES (STAGES * STG_BYTES)      // 92160

// Scratch (allocation-free rule: __device__ globals)
__device__ __half g_xh[(size_t)ROWS * DM];
__device__ __half g_wq[(size_t)DM * DM];
__device__ __half g_wk[(size_t)DM * DM];
__device__ __half g_wv[(size_t)DM * DM];
__device__ __half g_qh[(size_t)ROWS * DM];
__device__ __half g_kh[(size_t)ROWS * DM];
__device__ __half g_vt[(size_t)BATCH * DM * SEQ];  // V transposed per batch
__device__ float  g_s [(size_t)BATCH * SEQ * SEQ]; // fp32 scores
__device__ __half g_p [(size_t)BATCH * SEQ * SEQ]; // fp16 probs

__device__ __forceinline__ void mma16(float c[4], const unsigned a[4], const unsigned b[2]) {
    asm volatile(
        "mma.sync.aligned.m16n8k16.row.col.f32.f16.f16.f32 "
        "{%0,%1,%2,%3},{%4,%5,%6,%7},{%8,%9},{%0,%1,%2,%3};"
        : "+f"(c[0]), "+f"(c[1]), "+f"(c[2]), "+f"(c[3])
        : "r"(a[0]), "r"(a[1]), "r"(a[2]), "r"(a[3]), "r"(b[0]), "r"(b[1]));
}

__device__ __forceinline__ void ldsm_x4(unsigned r[4], unsigned addr) {
    asm volatile("ldmatrix.sync.aligned.m8n8.x4.shared.b16 {%0,%1,%2,%3}, [%4];"
        : "=r"(r[0]), "=r"(r[1]), "=r"(r[2]), "=r"(r[3]) : "r"(addr));
}

__device__ __forceinline__ void cp16(unsigned smem_u32, const void* gptr) {
    asm volatile("cp.async.cg.shared.global [%0], [%1], 16;\n" :: "r"(smem_u32), "l"(gptr));
}
__device__ __forceinline__ void cp_commit() { asm volatile("cp.async.commit_group;\n"); }
template<int N>
__device__ __forceinline__ void cp_wait() { asm volatile("cp.async.wait_group %0;\n" :: "n"(N)); }

// ---------------------------------------------------------------------------
// fp32 -> fp16 conversion (RN)
// ---------------------------------------------------------------------------
__global__ void cvt_f2h(const float* __restrict__ in, __half* __restrict__ out, int n4)
{
    int i = blockIdx.x * blockDim.x + threadIdx.x;
    if (i >= n4) return;
    float4 v = ((const float4*)in)[i];
    ((__half2*)out)[2 * i]     = __float22half2_rn(make_float2(v.x, v.y));
    ((__half2*)out)[2 * i + 1] = __float22half2_rn(make_float2(v.z, v.w));
}

// ---------------------------------------------------------------------------
// fp16 m16n8k16 GEMM, 128x256 CTA tile, 8 warps x (64x64), cp.async 3-stage.
// MODE 0: Ch = (A W^T + bias)           half out      (Q/K projections)
// MODE 3: Vt = (A W^T + bias)^T         half out      (V projection, transposed)
// MODE 1: S[b] = (Q K^T)/32             fp32 out, skip above-diag tiles
// MODE 2: O[b] = P Vt^T                 fp32 out, K limited by causality
// ---------------------------------------------------------------------------
template<int MODE>
__global__ __launch_bounds__(THREADS, 2) void mm_h(
    const __half* __restrict__ Ag, const __half* __restrict__ Bg,
    const float* __restrict__ bias, void* __restrict__ Cg)
{
    const int row0 = blockIdx.y * BM;
    const int col0 = blockIdx.x * BN;
    const __half* A = Ag;
    const __half* B = Bg;
    int ldA = DM, ldB = DM;
    if (MODE == 1) {
        if (col0 > row0) return;     // fully masked tile, never read downstream
        size_t off = (size_t)blockIdx.z * SEQ * DM;
        A += off; B += off;
    }
    if (MODE == 2) {
        A += (size_t)blockIdx.z * SEQ * SEQ;
        B += (size_t)blockIdx.z * DM * SEQ;
        ldA = SEQ; ldB = SEQ;
    }
    const int kEnd  = (MODE == 2) ? (row0 + BM) : DM;
    const int nIter = kEnd / BK;

    extern __shared__ __align__(16) __half smem_h[];
    const unsigned smem_base = (unsigned)__cvta_generic_to_shared(smem_h);

    const int tid = threadIdx.x;
    // cp.async: A 128x32 halves = 512 chunks (2/thread); B 256x32 = 1024 (4/thread)
    auto issue = [&](int it) {
        const int k0 = it * BK;
        const unsigned sa = smem_base + (it % STAGES) * STG_BYTES;
        const unsigned sb = sa + MAT_A_BYTES;
        #pragma unroll
        for (int t = 0; t < 2; ++t) {
            int cid = tid + t * THREADS;
            int r = cid >> 2, c8 = (cid & 3) * 8;
            cp16(sa + (r * LDH + c8) * 2, A + (size_t)(row0 + r) * ldA + k0 + c8);
        }
        #pragma unroll
        for (int t = 0; t < 4; ++t) {
            int cid = tid + t * THREADS;
            int r = cid >> 2, c8 = (cid & 3) * 8;
            cp16(sb + (r * LDH + c8) * 2, B + (size_t)(col0 + r) * ldB + k0 + c8);
        }
    };

    const int lane = tid & 31;
    const int wid = tid >> 5;
    const int wm = (wid >> 2) * 64;          // warp rows (2x4 warp grid)
    const int wn = (wid & 3) * 64;           // warp cols
    const int lq = lane >> 2, lr = lane & 3;

    // LDSM lane address components (halves)
    const int lr8 = lane & 7;
    // A x4: [rows0-7 k0-7, rows8-15 k0-7, rows0-7 k8-15, rows8-15 k8-15]
    const unsigned aoff = (unsigned)(((wm + lr8 + ((lane >> 3) & 1) * 8) * LDH
                                      + ((lane >> 4) & 1) * 8) * 2);
    // B x4: [n0-7 k0-7, n0-7 k8-15, n8-15 k0-7, n8-15 k8-15]
    const unsigned boff = (unsigned)(((wn + lr8 + ((lane >> 4) & 1) * 8) * LDH
                                      + ((lane >> 3) & 1) * 8) * 2);

    float acc[4][8][4] = {};   // 4 m-tiles x 8 n-tiles x 4 regs = 64x64 per warp

    #pragma unroll
    for (int s = 0; s < STAGES - 1; ++s) {
        if (s < nIter) issue(s);
        cp_commit();
    }

    for (int it = 0; it < nIter; ++it) {
        cp_wait<STAGES - 2>();
        __syncthreads();

        if (it + STAGES - 1 < nIter) issue(it + STAGES - 1);
        cp_commit();

        const unsigned sA = smem_base + (it % STAGES) * STG_BYTES;
        const unsigned sB = sA + MAT_A_BYTES;

        #pragma unroll
        for (int ks = 0; ks < 2; ++ks) {             // two k16 steps per BK=32
            unsigned af[4][4], bf[8][2];
            #pragma unroll
            for (int i = 0; i < 4; ++i)
                ldsm_x4(af[i], sA + aoff + (unsigned)((i * 16 * LDH + ks * 16) * 2));
            #pragma unroll
            for (int j2 = 0; j2 < 4; ++j2) {
                unsigned bb[4];
                ldsm_x4(bb, sB + boff + (unsigned)((j2 * 16 * LDH + ks * 16) * 2));
                bf[2 * j2][0] = bb[0]; bf[2 * j2][1] = bb[1];
                bf[2 * j2 + 1][0] = bb[2]; bf[2 * j2 + 1][1] = bb[3];
            }
            #pragma unroll
            for (int i = 0; i < 4; ++i)
                #pragma unroll
                for (int j = 0; j < 8; ++j)
                    mma16(acc[i][j], af[i], bf[j]);
        }
    }
    __syncthreads();   // all warps done with smem before epilogue reuses it

    // ------------------------------- epilogue -------------------------------
    if (MODE == 0) {
        __half* C = (__half*)Cg;
        #pragma unroll
        for (int i = 0; i < 4; ++i) {
            const int r = row0 + wm + i * 16 + lq;
            #pragma unroll
            for (int j = 0; j < 8; ++j) {
                const int c = col0 + wn + j * 8 + 2 * lr;
                const float b0 = bias[c], b1 = bias[c + 1];
                *(__half2*)&C[(size_t)r * DM + c] =
                    __float22half2_rn(make_float2(acc[i][j][0] + b0, acc[i][j][1] + b1));
                *(__half2*)&C[(size_t)(r + 8) * DM + c] =
                    __float22half2_rn(make_float2(acc[i][j][2] + b0, acc[i][j][3] + b1));
            }
        }
    } else if (MODE == 1) {
        float* C = (float*)Cg + (size_t)blockIdx.z * SEQ * SEQ;
        const float scale = 1.0f / 32.0f;
        #pragma unroll
        for (int i = 0; i < 4; ++i) {
            const int r = row0 + wm + i * 16 + lq;
            #pragma unroll
            for (int j = 0; j < 8; ++j) {
                const int c = col0 + wn + j * 8 + 2 * lr;
                *(float2*)&C[(size_t)r * SEQ + c] =
                    make_float2(acc[i][j][0] * scale, acc[i][j][1] * scale);
                *(float2*)&C[(size_t)(r + 8) * SEQ + c] =
                    make_float2(acc[i][j][2] * scale, acc[i][j][3] * scale);
            }
        }
    } else if (MODE == 2) {
        float* C = (float*)Cg + (size_t)blockIdx.z * SEQ * DM;
        #pragma unroll
        for (int i = 0; i < 4; ++i) {
            const int r = row0 + wm + i * 16 + lq;
            #pragma unroll
            for (int j = 0; j < 8; ++j) {
                const int c = col0 + wn + j * 8 + 2 * lr;
                *(float2*)&C[(size_t)r * DM + c] = make_float2(acc[i][j][0], acc[i][j][1]);
                *(float2*)&C[(size_t)(r + 8) * DM + c] = make_float2(acc[i][j][2], acc[i][j][3]);
            }
        }
    } else {
        // MODE 3: transposed store via per-warp smem staging (64n x 64m, pad 72)
        __half* ts = smem_h + (size_t)wid * 64 * 72;
        #pragma unroll
        for (int i = 0; i < 4; ++i) {
            const int ml = i * 16 + lq;
            #pragma unroll
            for (int j = 0; j < 8; ++j) {
                const int nl = j * 8 + 2 * lr;
                const int c = col0 + wn + nl;
                const float b0 = bias[c], b1 = bias[c + 1];
                ts[nl * 72 + ml]           = __float2half_rn(acc[i][j][0] + b0);
                ts[(nl + 1) * 72 + ml]     = __float2half_rn(acc[i][j][1] + b1);
                ts[nl * 72 + ml + 8]       = __float2half_rn(acc[i][j][2] + b0);
                ts[(nl + 1) * 72 + ml + 8] = __float2half_rn(acc[i][j][3] + b1);
            }
        }
        __syncwarp();
        __half* vtb = (__half*)Cg + (size_t)(row0 >> 11) * DM * SEQ;
        const int s0 = (row0 & (SEQ - 1)) + wm;
        #pragma unroll
        for (int nr2 = 0; nr2 < 2; ++nr2) {
            const int nr = lane + nr2 * 32;
            const int n = col0 + wn + nr;
            #pragma unroll
            for (int i8 = 0; i8 < 8; ++i8) {
                uint4 v = *(uint4*)&ts[nr * 72 + i8 * 8];
                *(uint4*)&vtb[(size_t)n * SEQ + s0 + i8 * 8] = v;
            }
        }
    }
}

// ---------------------------------------------------------------------------
// Online softmax: fp32 scores in, fp16 probs out (tail zeroed to 128-boundary).
// ---------------------------------------------------------------------------
__global__ __launch_bounds__(256) void softmax_kernel(
    const float* __restrict__ S, __half* __restrict__ P)
{
    __shared__ float redm[8], reds[8];
    const int r = blockIdx.x;
    const int qi = r & (SEQ - 1);
    const float* row = S + (size_t)r * SEQ;
    __half* prow = P + (size_t)r * SEQ;
    const int L = qi + 1;
    const int L4 = L >> 2;
    const float4* row4 = (const float4*)row;
    const int tid = threadIdx.x;
    const int wid = tid >> 5, lane = tid & 31;

    float m = -FLT_MAX, s = 0.0f;
    for (int j = tid; j < L4; j += 256) {
        float4 v = row4[j];
        float cm = fmaxf(fmaxf(v.x, v.y), fmaxf(v.z, v.w));
        float nm = fmaxf(m, cm);
        s = s * __expf(m - nm)
          + __expf(v.x - nm) + __expf(v.y - nm) + __expf(v.z - nm) + __expf(v.w - nm);
        m = nm;
    }
    for (int j = L4 * 4 + tid; j < L; j += 256) {
        float v = row[j];
        float nm = fmaxf(m, v);
        s = s * __expf(m - nm) + __expf(v - nm);
        m = nm;
    }
    #pragma unroll
    for (int o = 16; o; o >>= 1) {
        float m2 = __shfl_xor_sync(0xffffffffu, m, o);
        float s2 = __shfl_xor_sync(0xffffffffu, s, o);
        float nm = fmaxf(m, m2);
        s = s * __expf(m - nm) + s2 * __expf(m2 - nm);
        m = nm;
    }
    if (lane == 0) { redm[wid] = m; reds[wid] = s; }
    __syncthreads();
    float M = -FLT_MAX;
    #pragma unroll
    for (int w = 0; w < 8; ++w) M = fmaxf(M, redm[w]);
    float Stot = 0.0f;
    #pragma unroll
    for (int w = 0; w < 8; ++w) Stot += reds[w] * __expf(redm[w] - M);
    const float inv = 1.0f / Stot;

    for (int j = tid; j < L4; j += 256) {
        float4 v = row4[j];
        ((__half2*)prow)[2 * j] =
            __float22half2_rn(make_float2(__expf(v.x - M) * inv, __expf(v.y - M) * inv));
        ((__half2*)prow)[2 * j + 1] =
            __float22half2_rn(make_float2(__expf(v.z - M) * inv, __expf(v.w - M) * inv));
    }
    for (int j = L4 * 4 + tid; j < L; j += 256)
        prow[j] = __float2half_rn(__expf(row[j] - M) * inv);
    // Zero only up to the 128-boundary PV actually reads (kEnd = row0+128).
    const int zEnd = (qi & ~127) + 128;
    for (int j = L + tid; j < zEnd; j += 256) prow[j] = __float2half_rn(0.0f);
}

// ---------------------------------------------------------------------------
extern "C" void kernel_launch(void* const* d_in, const int* in_sizes, int n_in,
                              void* d_out, int out_size)
{
    (void)in_sizes; (void)n_in; (void)out_size;
    const float* x  = (const float*)d_in[0];
    const float* Wq = (const float*)d_in[1];
    const float* bq = (const float*)d_in[2];
    const float* Wk = (const float*)d_in[3];
    const float* bk = (const float*)d_in[4];
    const float* Wv = (const float*)d_in[5];
    const float* bv = (const float*)d_in[6];
    float* out = (float*)d_out;

    __half *xh, *wq, *wk, *wv, *qh, *kh, *vt, *p;
    float *s;
    cudaGetSymbolAddress((void**)&xh, g_xh);
    cudaGetSymbolAddress((void**)&wq, g_wq);
    cudaGetSymbolAddress((void**)&wk, g_wk);
    cudaGetSymbolAddress((void**)&wv, g_wv);
    cudaGetSymbolAddress((void**)&qh, g_qh);
    cudaGetSymbolAddress((void**)&kh, g_kh);
    cudaGetSymbolAddress((void**)&vt, g_vt);
    cudaGetSymbolAddress((void**)&p,  g_p);
    cudaGetSymbolAddress((void**)&s,  g_s);

    cudaFuncSetAttribute(mm_h<0>, cudaFuncAttributeMaxDynamicSharedMemorySize, SMEM_BYTES);
    cudaFuncSetAttribute(mm_h<1>, cudaFuncAttributeMaxDynamicSharedMemorySize, SMEM_BYTES);
    cudaFuncSetAttribute(mm_h<2>, cudaFuncAttributeMaxDynamicSharedMemorySize, SMEM_BYTES);
    cudaFuncSetAttribute(mm_h<3>, cudaFuncAttributeMaxDynamicSharedMemorySize, SMEM_BYTES);

    dim3 blk(THREADS);

    const int nX4 = ROWS * DM / 4, nW4 = DM * DM / 4;
    cvt_f2h<<<(nX4 + 255) / 256, 256>>>(x,  xh, nX4);
    cvt_f2h<<<(nW4 + 255) / 256, 256>>>(Wq, wq, nW4);
    cvt_f2h<<<(nW4 + 255) / 256, 256>>>(Wk, wk, nW4);
    cvt_f2h<<<(nW4 + 255) / 256, 256>>>(Wv, wv, nW4);

    // QKV projections (V written transposed)
    dim3 gProj(DM / BN, ROWS / BM);              // (4, 64) = 256 CTAs ~ 1 wave
    mm_h<0><<<gProj, blk, SMEM_BYTES>>>(xh, wq, bq, qh);
    mm_h<0><<<gProj, blk, SMEM_BYTES>>>(xh, wk, bk, kh);
    mm_h<3><<<gProj, blk, SMEM_BYTES>>>(xh, wv, bv, vt);

    // Causal scores (fp32 out): 72 live tiles x 4 batches = 288 CTAs ~ 1 wave
    dim3 gScores(SEQ / BN, SEQ / BM, BATCH);     // (8, 16, 4)
    mm_h<1><<<gScores, blk, SMEM_BYTES>>>(qh, kh, nullptr, s);

    // Row softmax (fp32 -> fp16 probs)
    softmax_kernel<<<ROWS, 256>>>(s, p);

    // O = P Vt^T (fp32 out): 256 CTAs ~ 1 wave
    dim3 gPV(DM / BN, SEQ / BM, BATCH);          // (4, 16, 4)
    mm_h<2><<<gPV, blk, SMEM_BYTES>>>(p, vt, nullptr, out);
}

// round 11
// speedup vs baseline: 2.6519x; 2.6519x over previous
#include <cuda_runtime.h>
#include <cuda_fp16.h>
#include <math.h>
#include <float.h>
#include <stdint.h>

#define BATCH 4
#define SEQ   2048
#define DM    1024
#define ROWS  (BATCH * SEQ)   // 8192

#define BM 128
#define BN 128
#define BK 32                 // halves per K-slice
#define LDH 40                // halves per smem row (80B; LDSM conflict-free)
#define THREADS 128
#define STAGES 3
#define MAT_BYTES (128 * LDH * 2)            // 10240 per matrix tile
#define STG_BYTES (2 * MAT_BYTES)            // 20480
#define SMEM_BYTES (STAGES * STG_BYTES)      // 61440

// Scratch (allocation-free rule: __device__ globals)
__device__ __half g_xh[(size_t)ROWS * DM];
__device__ __half g_wq[(size_t)DM * DM];
__device__ __half g_wk[(size_t)DM * DM];
__device__ __half g_wv[(size_t)DM * DM];
__device__ __half g_qh[(size_t)ROWS * DM];
__device__ __half g_kh[(size_t)ROWS * DM];
__device__ __half g_vt[(size_t)BATCH * DM * SEQ];  // V transposed per batch
__device__ float  g_s [(size_t)BATCH * SEQ * SEQ]; // fp32 scores
__device__ __half g_p [(size_t)BATCH * SEQ * SEQ]; // fp16 probs

__device__ __forceinline__ void mma16(float c[4], const unsigned a[4], const unsigned b[2]) {
    asm volatile(
        "mma.sync.aligned.m16n8k16.row.col.f32.f16.f16.f32 "
        "{%0,%1,%2,%3},{%4,%5,%6,%7},{%8,%9},{%0,%1,%2,%3};"
        : "+f"(c[0]), "+f"(c[1]), "+f"(c[2]), "+f"(c[3])
        : "r"(a[0]), "r"(a[1]), "r"(a[2]), "r"(a[3]), "r"(b[0]), "r"(b[1]));
}

__device__ __forceinline__ void ldsm_x4(unsigned r[4], unsigned addr) {
    asm volatile("ldmatrix.sync.aligned.m8n8.x4.shared.b16 {%0,%1,%2,%3}, [%4];"
        : "=r"(r[0]), "=r"(r[1]), "=r"(r[2]), "=r"(r[3]) : "r"(addr));
}

__device__ __forceinline__ void cp16(unsigned smem_u32, const void* gptr) {
    asm volatile("cp.async.cg.shared.global [%0], [%1], 16;\n" :: "r"(smem_u32), "l"(gptr));
}
__device__ __forceinline__ void cp_commit() { asm volatile("cp.async.commit_group;\n"); }
template<int N>
__device__ __forceinline__ void cp_wait() { asm volatile("cp.async.wait_group %0;\n" :: "n"(N)); }

// ---------------------------------------------------------------------------
// fp32 -> fp16 conversion (RN); 2x float4 in, 1x uint4 out per thread.
// ---------------------------------------------------------------------------
__global__ void cvt_f2h(const float* __restrict__ in, __half* __restrict__ out, int n8)
{
    int i = blockIdx.x * blockDim.x + threadIdx.x;
    if (i >= n8) return;
    float4 a = ((const float4*)in)[2 * i];
    float4 b = ((const float4*)in)[2 * i + 1];
    __half2 h0 = __float22half2_rn(make_float2(a.x, a.y));
    __half2 h1 = __float22half2_rn(make_float2(a.z, a.w));
    __half2 h2 = __float22half2_rn(make_float2(b.x, b.y));
    __half2 h3 = __float22half2_rn(make_float2(b.z, b.w));
    uint4 o;
    o.x = *(unsigned*)&h0; o.y = *(unsigned*)&h1;
    o.z = *(unsigned*)&h2; o.w = *(unsigned*)&h3;
    ((uint4*)out)[i] = o;
}

// ---------------------------------------------------------------------------
// Merged QKV projection: grid z picks weight/bias/output.
// z=0: q = x Wq^T + bq   (row-major half)
// z=1: k = x Wk^T + bk   (row-major half)
// z=2: vt = (x Wv^T + bv)^T  (transposed half, per-batch [DM, SEQ])
// Mainloop identical to the proven R9 kernel (128x128 tile, 4 warps x 64x64).
// ---------------------------------------------------------------------------
__global__ __launch_bounds__(THREADS, 2) void mm_qkv(
    const __half* __restrict__ A,
    const __half* __restrict__ Wq, const __half* __restrict__ Wk, const __half* __restrict__ Wv,
    const float* __restrict__ bqp, const float* __restrict__ bkp, const float* __restrict__ bvp,
    __half* __restrict__ Oq, __half* __restrict__ Ok, __half* __restrict__ Ovt)
{
    const int z = blockIdx.z;
    const __half* B = (z == 0) ? Wq : (z == 1) ? Wk : Wv;
    const float* bias = (z == 0) ? bqp : (z == 1) ? bkp : bvp;

    const int row0 = blockIdx.y * BM;
    const int col0 = blockIdx.x * BN;
    const int nIter = DM / BK;

    extern __shared__ __align__(16) __half smem_h[];
    const unsigned smem_base = (unsigned)__cvta_generic_to_shared(smem_h);

    const int tid = threadIdx.x;
    auto issue = [&](int it) {
        const int k0 = it * BK;
        const unsigned sa = smem_base + (it % STAGES) * STG_BYTES;
        const unsigned sb = sa + MAT_BYTES;
        #pragma unroll
        for (int t = 0; t < 4; ++t) {
            int cid = tid + t * THREADS;
            int r = cid >> 2, c8 = (cid & 3) * 8;
            cp16(sa + (r * LDH + c8) * 2, A + (size_t)(row0 + r) * DM + k0 + c8);
        }
        #pragma unroll
        for (int t = 0; t < 4; ++t) {
            int cid = tid + t * THREADS;
            int r = cid >> 2, c8 = (cid & 3) * 8;
            cp16(sb + (r * LDH + c8) * 2, B + (size_t)(col0 + r) * DM + k0 + c8);
        }
    };

    const int lane = tid & 31;
    const int wid = tid >> 5;
    const int wm = (wid >> 1) * 64;
    const int wn = (wid & 1) * 64;
    const int lq = lane >> 2, lr = lane & 3;

    const int lr8 = lane & 7;
    const unsigned aoff = (unsigned)(((wm + lr8 + ((lane >> 3) & 1) * 8) * LDH
                                      + ((lane >> 4) & 1) * 8) * 2);
    const unsigned boff = (unsigned)(((wn + lr8 + ((lane >> 4) & 1) * 8) * LDH
                                      + ((lane >> 3) & 1) * 8) * 2);

    float acc[4][8][4] = {};

    #pragma unroll
    for (int s = 0; s < STAGES - 1; ++s) {
        issue(s);
        cp_commit();
    }

    for (int it = 0; it < nIter; ++it) {
        cp_wait<STAGES - 2>();
        __syncthreads();

        if (it + STAGES - 1 < nIter) issue(it + STAGES - 1);
        cp_commit();

        const unsigned sA = smem_base + (it % STAGES) * STG_BYTES;
        const unsigned sB = sA + MAT_BYTES;

        #pragma unroll
        for (int ks = 0; ks < 2; ++ks) {
            unsigned af[4][4], bf[8][2];
            #pragma unroll
            for (int i = 0; i < 4; ++i)
                ldsm_x4(af[i], sA + aoff + (unsigned)((i * 16 * LDH + ks * 16) * 2));
            #pragma unroll
            for (int j2 = 0; j2 < 4; ++j2) {
                unsigned bb[4];
                ldsm_x4(bb, sB + boff + (unsigned)((j2 * 16 * LDH + ks * 16) * 2));
                bf[2 * j2][0] = bb[0]; bf[2 * j2][1] = bb[1];
                bf[2 * j2 + 1][0] = bb[2]; bf[2 * j2 + 1][1] = bb[3];
            }
            #pragma unroll
            for (int i = 0; i < 4; ++i)
                #pragma unroll
                for (int j = 0; j < 8; ++j)
                    mma16(acc[i][j], af[i], bf[j]);
        }
    }
    __syncthreads();

    if (z < 2) {
        __half* C = (z == 0) ? Oq : Ok;
        #pragma unroll
        for (int i = 0; i < 4; ++i) {
            const int r = row0 + wm + i * 16 + lq;
            #pragma unroll
            for (int j = 0; j < 8; ++j) {
                const int c = col0 + wn + j * 8 + 2 * lr;
                const float b0 = bias[c], b1 = bias[c + 1];
                *(__half2*)&C[(size_t)r * DM + c] =
                    __float22half2_rn(make_float2(acc[i][j][0] + b0, acc[i][j][1] + b1));
                *(__half2*)&C[(size_t)(r + 8) * DM + c] =
                    __float22half2_rn(make_float2(acc[i][j][2] + b0, acc[i][j][3] + b1));
            }
        }
    } else {
        // transposed store via per-warp smem staging (64n x 64m, pad 72)
        __half* ts = smem_h + (size_t)wid * 64 * 72;
        #pragma unroll
        for (int i = 0; i < 4; ++i) {
            const int ml = i * 16 + lq;
            #pragma unroll
            for (int j = 0; j < 8; ++j) {
                const int nl = j * 8 + 2 * lr;
                const int c = col0 + wn + nl;
                const float b0 = bias[c], b1 = bias[c + 1];
                ts[nl * 72 + ml]           = __float2half_rn(acc[i][j][0] + b0);
                ts[(nl + 1) * 72 + ml]     = __float2half_rn(acc[i][j][1] + b1);
                ts[nl * 72 + ml + 8]       = __float2half_rn(acc[i][j][2] + b0);
                ts[(nl + 1) * 72 + ml + 8] = __float2half_rn(acc[i][j][3] + b1);
            }
        }
        __syncwarp();
        __half* vtb = Ovt + (size_t)(row0 >> 11) * DM * SEQ;
        const int s0 = (row0 & (SEQ - 1)) + wm;
        #pragma unroll
        for (int nr2 = 0; nr2 < 2; ++nr2) {
            const int nr = lane + nr2 * 32;
            const int n = col0 + wn + nr;
            #pragma unroll
            for (int i8 = 0; i8 < 8; ++i8) {
                uint4 v = *(uint4*)&ts[nr * 72 + i8 * 8];
                *(uint4*)&vtb[(size_t)n * SEQ + s0 + i8 * 8] = v;
            }
        }
    }
}

// ---------------------------------------------------------------------------
// fp16 m16n8k16 GEMM (R9-proven), 128x128 tile, 4 warps x (64x64).
// MODE 1: S[b] = (Q K^T)/32             fp32 out, skip above-diag tiles
// MODE 2: O[b] = P Vt^T                 fp32 out, K limited by causality;
//                                        longest-first CTA order (reversed y)
// ---------------------------------------------------------------------------
template<int MODE>
__global__ __launch_bounds__(THREADS, 2) void mm_h(
    const __half* __restrict__ Ag, const __half* __restrict__ Bg,
    void* __restrict__ Cg)
{
    const int by = (MODE == 2) ? ((int)gridDim.y - 1 - (int)blockIdx.y) : (int)blockIdx.y;
    const int row0 = by * BM;
    const int col0 = blockIdx.x * BN;
    const __half* A = Ag;
    const __half* B = Bg;
    int ldA = DM, ldB = DM;
    if (MODE == 1) {
        if (col0 > row0) return;     // fully masked tile, never read downstream
        size_t off = (size_t)blockIdx.z * SEQ * DM;
        A += off; B += off;
    }
    if (MODE == 2) {
        A += (size_t)blockIdx.z * SEQ * SEQ;
        B += (size_t)blockIdx.z * DM * SEQ;
        ldA = SEQ; ldB = SEQ;
    }
    const int kEnd  = (MODE == 2) ? (row0 + BM) : DM;
    const int nIter = kEnd / BK;

    extern __shared__ __align__(16) __half smem_h[];
    const unsigned smem_base = (unsigned)__cvta_generic_to_shared(smem_h);

    const int tid = threadIdx.x;
    auto issue = [&](int it) {
        const int k0 = it * BK;
        const unsigned sa = smem_base + (it % STAGES) * STG_BYTES;
        const unsigned sb = sa + MAT_BYTES;
        #pragma unroll
        for (int t = 0; t < 4; ++t) {
            int cid = tid + t * THREADS;
            int r = cid >> 2, c8 = (cid & 3) * 8;
            cp16(sa + (r * LDH + c8) * 2, A + (size_t)(row0 + r) * ldA + k0 + c8);
        }
        #pragma unroll
        for (int t = 0; t < 4; ++t) {
            int cid = tid + t * THREADS;
            int r = cid >> 2, c8 = (cid & 3) * 8;
            cp16(sb + (r * LDH + c8) * 2, B + (size_t)(col0 + r) * ldB + k0 + c8);
        }
    };

    const int lane = tid & 31;
    const int wid = tid >> 5;
    const int wm = (wid >> 1) * 64;
    const int wn = (wid & 1) * 64;
    const int lq = lane >> 2, lr = lane & 3;

    const int lr8 = lane & 7;
    const unsigned aoff = (unsigned)(((wm + lr8 + ((lane >> 3) & 1) * 8) * LDH
                                      + ((lane >> 4) & 1) * 8) * 2);
    const unsigned boff = (unsigned)(((wn + lr8 + ((lane >> 4) & 1) * 8) * LDH
                                      + ((lane >> 3) & 1) * 8) * 2);

    float acc[4][8][4] = {};

    #pragma unroll
    for (int s = 0; s < STAGES - 1; ++s) {
        if (s < nIter) issue(s);
        cp_commit();
    }

    for (int it = 0; it < nIter; ++it) {
        cp_wait<STAGES - 2>();
        __syncthreads();

        if (it + STAGES - 1 < nIter) issue(it + STAGES - 1);
        cp_commit();

        const unsigned sA = smem_base + (it % STAGES) * STG_BYTES;
        const unsigned sB = sA + MAT_BYTES;

        #pragma unroll
        for (int ks = 0; ks < 2; ++ks) {
            unsigned af[4][4], bf[8][2];
            #pragma unroll
            for (int i = 0; i < 4; ++i)
                ldsm_x4(af[i], sA + aoff + (unsigned)((i * 16 * LDH + ks * 16) * 2));
            #pragma unroll
            for (int j2 = 0; j2 < 4; ++j2) {
                unsigned bb[4];
                ldsm_x4(bb, sB + boff + (unsigned)((j2 * 16 * LDH + ks * 16) * 2));
                bf[2 * j2][0] = bb[0]; bf[2 * j2][1] = bb[1];
                bf[2 * j2 + 1][0] = bb[2]; bf[2 * j2 + 1][1] = bb[3];
            }
            #pragma unroll
            for (int i = 0; i < 4; ++i)
                #pragma unroll
                for (int j = 0; j < 8; ++j)
                    mma16(acc[i][j], af[i], bf[j]);
        }
    }

    if (MODE == 1) {
        float* C = (float*)Cg + (size_t)blockIdx.z * SEQ * SEQ;
        const float scale = 1.0f / 32.0f;
        #pragma unroll
        for (int i = 0; i < 4; ++i) {
            const int r = row0 + wm + i * 16 + lq;
            #pragma unroll
            for (int j = 0; j < 8; ++j) {
                const int c = col0 + wn + j * 8 + 2 * lr;
                *(float2*)&C[(size_t)r * SEQ + c] =
                    make_float2(acc[i][j][0] * scale, acc[i][j][1] * scale);
                *(float2*)&C[(size_t)(r + 8) * SEQ + c] =
                    make_float2(acc[i][j][2] * scale, acc[i][j][3] * scale);
            }
        }
    } else {
        float* C = (float*)Cg + (size_t)blockIdx.z * SEQ * DM;
        #pragma unroll
        for (int i = 0; i < 4; ++i) {
            const int r = row0 + wm + i * 16 + lq;
            #pragma unroll
            for (int j = 0; j < 8; ++j) {
                const int c = col0 + wn + j * 8 + 2 * lr;
                *(float2*)&C[(size_t)r * DM + c] = make_float2(acc[i][j][0], acc[i][j][1]);
                *(float2*)&C[(size_t)(r + 8) * DM + c] = make_float2(acc[i][j][2], acc[i][j][3]);
            }
        }
    }
}

// ---------------------------------------------------------------------------
// Online softmax: fp32 scores in, fp16 probs out (tail zeroed to 128-boundary).
// ---------------------------------------------------------------------------
__global__ __launch_bounds__(256) void softmax_kernel(
    const float* __restrict__ S, __half* __restrict__ P)
{
    __shared__ float redm[8], reds[8];
    const int r = blockIdx.x;
    const int qi = r & (SEQ - 1);
    const float* row = S + (size_t)r * SEQ;
    __half* prow = P + (size_t)r * SEQ;
    const int L = qi + 1;
    const int L4 = L >> 2;
    const float4* row4 = (const float4*)row;
    const int tid = threadIdx.x;
    const int wid = tid >> 5, lane = tid & 31;

    float m = -FLT_MAX, s = 0.0f;
    for (int j = tid; j < L4; j += 256) {
        float4 v = row4[j];
        float cm = fmaxf(fmaxf(v.x, v.y), fmaxf(v.z, v.w));
        float nm = fmaxf(m, cm);
        s = s * __expf(m - nm)
          + __expf(v.x - nm) + __expf(v.y - nm) + __expf(v.z - nm) + __expf(v.w - nm);
        m = nm;
    }
    for (int j = L4 * 4 + tid; j < L; j += 256) {
        float v = row[j];
        float nm = fmaxf(m, v);
        s = s * __expf(m - nm) + __expf(v - nm);
        m = nm;
    }
    #pragma unroll
    for (int o = 16; o; o >>= 1) {
        float m2 = __shfl_xor_sync(0xffffffffu, m, o);
        float s2 = __shfl_xor_sync(0xffffffffu, s, o);
        float nm = fmaxf(m, m2);
        s = s * __expf(m - nm) + s2 * __expf(m2 - nm);
        m = nm;
    }
    if (lane == 0) { redm[wid] = m; reds[wid] = s; }
    __syncthreads();
    float M = -FLT_MAX;
    #pragma unroll
    for (int w = 0; w < 8; ++w) M = fmaxf(M, redm[w]);
    float Stot = 0.0f;
    #pragma unroll
    for (int w = 0; w < 8; ++w) Stot += reds[w] * __expf(redm[w] - M);
    const float inv = 1.0f / Stot;

    for (int j = tid; j < L4; j += 256) {
        float4 v = row4[j];
        ((__half2*)prow)[2 * j] =
            __float22half2_rn(make_float2(__expf(v.x - M) * inv, __expf(v.y - M) * inv));
        ((__half2*)prow)[2 * j + 1] =
            __float22half2_rn(make_float2(__expf(v.z - M) * inv, __expf(v.w - M) * inv));
    }
    for (int j = L4 * 4 + tid; j < L; j += 256)
        prow[j] = __float2half_rn(__expf(row[j] - M) * inv);
    // Zero only up to the 128-boundary PV actually reads (kEnd = row0+128).
    const int zEnd = (qi & ~127) + 128;
    for (int j = L + tid; j < zEnd; j += 256) prow[j] = __float2half_rn(0.0f);
}

// ---------------------------------------------------------------------------
extern "C" void kernel_launch(void* const* d_in, const int* in_sizes, int n_in,
                              void* d_out, int out_size)
{
    (void)in_sizes; (void)n_in; (void)out_size;
    const float* x  = (const float*)d_in[0];
    const float* Wq = (const float*)d_in[1];
    const float* bq = (const float*)d_in[2];
    const float* Wk = (const float*)d_in[3];
    const float* bk = (const float*)d_in[4];
    const float* Wv = (const float*)d_in[5];
    const float* bv = (const float*)d_in[6];
    float* out = (float*)d_out;

    __half *xh, *wq, *wk, *wv, *qh, *kh, *vt, *p;
    float *s;
    cudaGetSymbolAddress((void**)&xh, g_xh);
    cudaGetSymbolAddress((void**)&wq, g_wq);
    cudaGetSymbolAddress((void**)&wk, g_wk);
    cudaGetSymbolAddress((void**)&wv, g_wv);
    cudaGetSymbolAddress((void**)&qh, g_qh);
    cudaGetSymbolAddress((void**)&kh, g_kh);
    cudaGetSymbolAddress((void**)&vt, g_vt);
    cudaGetSymbolAddress((void**)&p,  g_p);
    cudaGetSymbolAddress((void**)&s,  g_s);

    cudaFuncSetAttribute(mm_qkv,  cudaFuncAttributeMaxDynamicSharedMemorySize, SMEM_BYTES);
    cudaFuncSetAttribute(mm_h<1>, cudaFuncAttributeMaxDynamicSharedMemorySize, SMEM_BYTES);
    cudaFuncSetAttribute(mm_h<2>, cudaFuncAttributeMaxDynamicSharedMemorySize, SMEM_BYTES);

    dim3 blk(THREADS);

    const int nX8 = ROWS * DM / 8, nW8 = DM * DM / 8;
    cvt_f2h<<<(nX8 + 255) / 256, 256>>>(x,  xh, nX8);
    cvt_f2h<<<(nW8 + 255) / 256, 256>>>(Wq, wq, nW8);
    cvt_f2h<<<(nW8 + 255) / 256, 256>>>(Wk, wk, nW8);
    cvt_f2h<<<(nW8 + 255) / 256, 256>>>(Wv, wv, nW8);

    // Merged QKV projections (V written transposed): (8, 64, 3) = 1536 CTAs
    dim3 gProj(DM / BN, ROWS / BM, 3);
    mm_qkv<<<gProj, blk, SMEM_BYTES>>>(xh, wq, wk, wv, bq, bk, bv, qh, kh, vt);

    // Causal scores (fp32 out)
    dim3 gScores(SEQ / BN, SEQ / BM, BATCH);     // (16, 16, 4)
    mm_h<1><<<gScores, blk, SMEM_BYTES>>>(qh, kh, s);

    // Row softmax (fp32 -> fp16 probs)
    softmax_kernel<<<ROWS, 256>>>(s, p);

    // O = P Vt^T (fp32 out), longest CTAs first
    dim3 gPV(DM / BN, SEQ / BM, BATCH);          // (8, 16, 4)
    mm_h<2><<<gPV, blk, SMEM_BYTES>>>(p, vt, out);
}

// round 12
// speedup vs baseline: 2.7598x; 1.0407x over previous
#include <cuda_runtime.h>
#include <cuda_fp16.h>
#include <math.h>
#include <float.h>
#include <stdint.h>

#define BATCH 4
#define SEQ   2048
#define DM    1024
#define ROWS  (BATCH * SEQ)   // 8192

#define BM 128
#define BN 128
#define BK 32                 // halves per K-slice
#define LDH 40                // halves per smem row (80B; LDSM conflict-free)
#define THREADS 128
#define STAGES 4
#define MAT_BYTES (128 * LDH * 2)            // 10240 per matrix tile
#define STG_BYTES (2 * MAT_BYTES)            // 20480
#define SMEM_BYTES (STAGES * STG_BYTES)      // 81920

// Scratch (allocation-free rule: __device__ globals)
__device__ __half g_xh[(size_t)ROWS * DM];
__device__ __half g_wq[(size_t)DM * DM];
__device__ __half g_wk[(size_t)DM * DM];
__device__ __half g_wv[(size_t)DM * DM];
__device__ __half g_qh[(size_t)ROWS * DM];
__device__ __half g_kh[(size_t)ROWS * DM];
__device__ __half g_vt[(size_t)BATCH * DM * SEQ];  // V transposed per batch
__device__ float  g_s [(size_t)BATCH * SEQ * SEQ]; // fp32 scores
__device__ __half g_p [(size_t)BATCH * SEQ * SEQ]; // fp16 probs

__device__ __forceinline__ void mma16(float c[4], const unsigned a[4], const unsigned b[2]) {
    asm volatile(
        "mma.sync.aligned.m16n8k16.row.col.f32.f16.f16.f32 "
        "{%0,%1,%2,%3},{%4,%5,%6,%7},{%8,%9},{%0,%1,%2,%3};"
        : "+f"(c[0]), "+f"(c[1]), "+f"(c[2]), "+f"(c[3])
        : "r"(a[0]), "r"(a[1]), "r"(a[2]), "r"(a[3]), "r"(b[0]), "r"(b[1]));
}

__device__ __forceinline__ void ldsm_x4(unsigned r[4], unsigned addr) {
    asm volatile("ldmatrix.sync.aligned.m8n8.x4.shared.b16 {%0,%1,%2,%3}, [%4];"
        : "=r"(r[0]), "=r"(r[1]), "=r"(r[2]), "=r"(r[3]) : "r"(addr));
}

__device__ __forceinline__ void cp16(unsigned smem_u32, const void* gptr) {
    asm volatile("cp.async.cg.shared.global [%0], [%1], 16;\n" :: "r"(smem_u32), "l"(gptr));
}
__device__ __forceinline__ void cp_commit() { asm volatile("cp.async.commit_group;\n"); }
template<int N>
__device__ __forceinline__ void cp_wait() { asm volatile("cp.async.wait_group %0;\n" :: "n"(N)); }

// ---------------------------------------------------------------------------
// Merged fp32 -> fp16 conversion of x, Wq, Wk, Wv (one launch).
// Index space in 8-element units.
// ---------------------------------------------------------------------------
#define NX8 (ROWS * DM / 8)   // 1048576
#define NW8 (DM * DM / 8)     // 131072

__global__ void cvt_all(const float* __restrict__ x,
                        const float* __restrict__ Wq, const float* __restrict__ Wk,
                        const float* __restrict__ Wv,
                        __half* __restrict__ xh, __half* __restrict__ wq,
                        __half* __restrict__ wk, __half* __restrict__ wv)
{
    int i = blockIdx.x * blockDim.x + threadIdx.x;
    const float* in;
    __half* out;
    int j;
    if (i < NX8)                { in = x;  out = xh; j = i; }
    else if (i < NX8 + NW8)     { in = Wq; out = wq; j = i - NX8; }
    else if (i < NX8 + 2 * NW8) { in = Wk; out = wk; j = i - NX8 - NW8; }
    else if (i < NX8 + 3 * NW8) { in = Wv; out = wv; j = i - NX8 - 2 * NW8; }
    else return;

    float4 a = ((const float4*)in)[2 * j];
    float4 b = ((const float4*)in)[2 * j + 1];
    __half2 h0 = __float22half2_rn(make_float2(a.x, a.y));
    __half2 h1 = __float22half2_rn(make_float2(a.z, a.w));
    __half2 h2 = __float22half2_rn(make_float2(b.x, b.y));
    __half2 h3 = __float22half2_rn(make_float2(b.z, b.w));
    uint4 o;
    o.x = *(unsigned*)&h0; o.y = *(unsigned*)&h1;
    o.z = *(unsigned*)&h2; o.w = *(unsigned*)&h3;
    ((uint4*)out)[j] = o;
}

// ---------------------------------------------------------------------------
// Merged QKV projection (R11-proven mainloop, STAGES=4).
// z=0: q = x Wq^T + bq ; z=1: k = x Wk^T + bk ; z=2: vt = (x Wv^T + bv)^T
// ---------------------------------------------------------------------------
__global__ __launch_bounds__(THREADS, 2) void mm_qkv(
    const __half* __restrict__ A,
    const __half* __restrict__ Wq, const __half* __restrict__ Wk, const __half* __restrict__ Wv,
    const float* __restrict__ bqp, const float* __restrict__ bkp, const float* __restrict__ bvp,
    __half* __restrict__ Oq, __half* __restrict__ Ok, __half* __restrict__ Ovt)
{
    const int z = blockIdx.z;
    const __half* B = (z == 0) ? Wq : (z == 1) ? Wk : Wv;
    const float* bias = (z == 0) ? bqp : (z == 1) ? bkp : bvp;

    const int row0 = blockIdx.y * BM;
    const int col0 = blockIdx.x * BN;
    const int nIter = DM / BK;

    extern __shared__ __align__(16) __half smem_h[];
    const unsigned smem_base = (unsigned)__cvta_generic_to_shared(smem_h);

    const int tid = threadIdx.x;
    auto issue = [&](int it) {
        const int k0 = it * BK;
        const unsigned sa = smem_base + (it % STAGES) * STG_BYTES;
        const unsigned sb = sa + MAT_BYTES;
        #pragma unroll
        for (int t = 0; t < 4; ++t) {
            int cid = tid + t * THREADS;
            int r = cid >> 2, c8 = (cid & 3) * 8;
            cp16(sa + (r * LDH + c8) * 2, A + (size_t)(row0 + r) * DM + k0 + c8);
        }
        #pragma unroll
        for (int t = 0; t < 4; ++t) {
            int cid = tid + t * THREADS;
            int r = cid >> 2, c8 = (cid & 3) * 8;
            cp16(sb + (r * LDH + c8) * 2, B + (size_t)(col0 + r) * DM + k0 + c8);
        }
    };

    const int lane = tid & 31;
    const int wid = tid >> 5;
    const int wm = (wid >> 1) * 64;
    const int wn = (wid & 1) * 64;
    const int lq = lane >> 2, lr = lane & 3;

    const int lr8 = lane & 7;
    const unsigned aoff = (unsigned)(((wm + lr8 + ((lane >> 3) & 1) * 8) * LDH
                                      + ((lane >> 4) & 1) * 8) * 2);
    const unsigned boff = (unsigned)(((wn + lr8 + ((lane >> 4) & 1) * 8) * LDH
                                      + ((lane >> 3) & 1) * 8) * 2);

    float acc[4][8][4] = {};

    #pragma unroll
    for (int s = 0; s < STAGES - 1; ++s) {
        issue(s);
        cp_commit();
    }

    for (int it = 0; it < nIter; ++it) {
        cp_wait<STAGES - 2>();
        __syncthreads();

        if (it + STAGES - 1 < nIter) issue(it + STAGES - 1);
        cp_commit();

        const unsigned sA = smem_base + (it % STAGES) * STG_BYTES;
        const unsigned sB = sA + MAT_BYTES;

        #pragma unroll
        for (int ks = 0; ks < 2; ++ks) {
            unsigned af[4][4], bf[8][2];
            #pragma unroll
            for (int i = 0; i < 4; ++i)
                ldsm_x4(af[i], sA + aoff + (unsigned)((i * 16 * LDH + ks * 16) * 2));
            #pragma unroll
            for (int j2 = 0; j2 < 4; ++j2) {
                unsigned bb[4];
                ldsm_x4(bb, sB + boff + (unsigned)((j2 * 16 * LDH + ks * 16) * 2));
                bf[2 * j2][0] = bb[0]; bf[2 * j2][1] = bb[1];
                bf[2 * j2 + 1][0] = bb[2]; bf[2 * j2 + 1][1] = bb[3];
            }
            #pragma unroll
            for (int i = 0; i < 4; ++i)
                #pragma unroll
                for (int j = 0; j < 8; ++j)
                    mma16(acc[i][j], af[i], bf[j]);
        }
    }
    __syncthreads();

    if (z < 2) {
        __half* C = (z == 0) ? Oq : Ok;
        #pragma unroll
        for (int i = 0; i < 4; ++i) {
            const int r = row0 + wm + i * 16 + lq;
            #pragma unroll
            for (int j = 0; j < 8; ++j) {
                const int c = col0 + wn + j * 8 + 2 * lr;
                const float b0 = bias[c], b1 = bias[c + 1];
                *(__half2*)&C[(size_t)r * DM + c] =
                    __float22half2_rn(make_float2(acc[i][j][0] + b0, acc[i][j][1] + b1));
                *(__half2*)&C[(size_t)(r + 8) * DM + c] =
                    __float22half2_rn(make_float2(acc[i][j][2] + b0, acc[i][j][3] + b1));
            }
        }
    } else {
        // transposed store via per-warp smem staging (64n x 64m, pad 72)
        __half* ts = smem_h + (size_t)wid * 64 * 72;
        #pragma unroll
        for (int i = 0; i < 4; ++i) {
            const int ml = i * 16 + lq;
            #pragma unroll
            for (int j = 0; j < 8; ++j) {
                const int nl = j * 8 + 2 * lr;
                const int c = col0 + wn + nl;
                const float b0 = bias[c], b1 = bias[c + 1];
                ts[nl * 72 + ml]           = __float2half_rn(acc[i][j][0] + b0);
                ts[(nl + 1) * 72 + ml]     = __float2half_rn(acc[i][j][1] + b1);
                ts[nl * 72 + ml + 8]       = __float2half_rn(acc[i][j][2] + b0);
                ts[(nl + 1) * 72 + ml + 8] = __float2half_rn(acc[i][j][3] + b1);
            }
        }
        __syncwarp();
        __half* vtb = Ovt + (size_t)(row0 >> 11) * DM * SEQ;
        const int s0 = (row0 & (SEQ - 1)) + wm;
        #pragma unroll
        for (int nr2 = 0; nr2 < 2; ++nr2) {
            const int nr = lane + nr2 * 32;
            const int n = col0 + wn + nr;
            #pragma unroll
            for (int i8 = 0; i8 < 8; ++i8) {
                uint4 v = *(uint4*)&ts[nr * 72 + i8 * 8];
                *(uint4*)&vtb[(size_t)n * SEQ + s0 + i8 * 8] = v;
            }
        }
    }
}

// ---------------------------------------------------------------------------
// fp16 m16n8k16 GEMM (R11-proven, STAGES=4).
// MODE 1: S[b] = (Q K^T)/32    fp32 out, skip above-diag tiles
// MODE 2: O[b] = P Vt^T        fp32 out, causal K-limit, longest-first order
// ---------------------------------------------------------------------------
template<int MODE>
__global__ __launch_bounds__(THREADS, 2) void mm_h(
    const __half* __restrict__ Ag, const __half* __restrict__ Bg,
    void* __restrict__ Cg)
{
    const int by = (MODE == 2) ? ((int)gridDim.y - 1 - (int)blockIdx.y) : (int)blockIdx.y;
    const int row0 = by * BM;
    const int col0 = blockIdx.x * BN;
    const __half* A = Ag;
    const __half* B = Bg;
    int ldA = DM, ldB = DM;
    if (MODE == 1) {
        if (col0 > row0) return;
        size_t off = (size_t)blockIdx.z * SEQ * DM;
        A += off; B += off;
    }
    if (MODE == 2) {
        A += (size_t)blockIdx.z * SEQ * SEQ;
        B += (size_t)blockIdx.z * DM * SEQ;
        ldA = SEQ; ldB = SEQ;
    }
    const int kEnd  = (MODE == 2) ? (row0 + BM) : DM;
    const int nIter = kEnd / BK;

    extern __shared__ __align__(16) __half smem_h[];
    const unsigned smem_base = (unsigned)__cvta_generic_to_shared(smem_h);

    const int tid = threadIdx.x;
    auto issue = [&](int it) {
        const int k0 = it * BK;
        const unsigned sa = smem_base + (it % STAGES) * STG_BYTES;
        const unsigned sb = sa + MAT_BYTES;
        #pragma unroll
        for (int t = 0; t < 4; ++t) {
            int cid = tid + t * THREADS;
            int r = cid >> 2, c8 = (cid & 3) * 8;
            cp16(sa + (r * LDH + c8) * 2, A + (size_t)(row0 + r) * ldA + k0 + c8);
        }
        #pragma unroll
        for (int t = 0; t < 4; ++t) {
            int cid = tid + t * THREADS;
            int r = cid >> 2, c8 = (cid & 3) * 8;
            cp16(sb + (r * LDH + c8) * 2, B + (size_t)(col0 + r) * ldB + k0 + c8);
        }
    };

    const int lane = tid & 31;
    const int wid = tid >> 5;
    const int wm = (wid >> 1) * 64;
    const int wn = (wid & 1) * 64;
    const int lq = lane >> 2, lr = lane & 3;

    const int lr8 = lane & 7;
    const unsigned aoff = (unsigned)(((wm + lr8 + ((lane >> 3) & 1) * 8) * LDH
                                      + ((lane >> 4) & 1) * 8) * 2);
    const unsigned boff = (unsigned)(((wn + lr8 + ((lane >> 4) & 1) * 8) * LDH
                                      + ((lane >> 3) & 1) * 8) * 2);

    float acc[4][8][4] = {};

    #pragma unroll
    for (int s = 0; s < STAGES - 1; ++s) {
        if (s < nIter) issue(s);
        cp_commit();
    }

    for (int it = 0; it < nIter; ++it) {
        cp_wait<STAGES - 2>();
        __syncthreads();

        if (it + STAGES - 1 < nIter) issue(it + STAGES - 1);
        cp_commit();

        const unsigned sA = smem_base + (it % STAGES) * STG_BYTES;
        const unsigned sB = sA + MAT_BYTES;

        #pragma unroll
        for (int ks = 0; ks < 2; ++ks) {
            unsigned af[4][4], bf[8][2];
            #pragma unroll
            for (int i = 0; i < 4; ++i)
                ldsm_x4(af[i], sA + aoff + (unsigned)((i * 16 * LDH + ks * 16) * 2));
            #pragma unroll
            for (int j2 = 0; j2 < 4; ++j2) {
                unsigned bb[4];
                ldsm_x4(bb, sB + boff + (unsigned)((j2 * 16 * LDH + ks * 16) * 2));
                bf[2 * j2][0] = bb[0]; bf[2 * j2][1] = bb[1];
                bf[2 * j2 + 1][0] = bb[2]; bf[2 * j2 + 1][1] = bb[3];
            }
            #pragma unroll
            for (int i = 0; i < 4; ++i)
                #pragma unroll
                for (int j = 0; j < 8; ++j)
                    mma16(acc[i][j], af[i], bf[j]);
        }
    }

    if (MODE == 1) {
        float* C = (float*)Cg + (size_t)blockIdx.z * SEQ * SEQ;
        const float scale = 1.0f / 32.0f;
        #pragma unroll
        for (int i = 0; i < 4; ++i) {
            const int r = row0 + wm + i * 16 + lq;
            #pragma unroll
            for (int j = 0; j < 8; ++j) {
                const int c = col0 + wn + j * 8 + 2 * lr;
                *(float2*)&C[(size_t)r * SEQ + c] =
                    make_float2(acc[i][j][0] * scale, acc[i][j][1] * scale);
                *(float2*)&C[(size_t)(r + 8) * SEQ + c] =
                    make_float2(acc[i][j][2] * scale, acc[i][j][3] * scale);
            }
        }
    } else {
        float* C = (float*)Cg + (size_t)blockIdx.z * SEQ * DM;
        #pragma unroll
        for (int i = 0; i < 4; ++i) {
            const int r = row0 + wm + i * 16 + lq;
            #pragma unroll
            for (int j = 0; j < 8; ++j) {
                const int c = col0 + wn + j * 8 + 2 * lr;
                *(float2*)&C[(size_t)r * DM + c] = make_float2(acc[i][j][0], acc[i][j][1]);
                *(float2*)&C[(size_t)(r + 8) * DM + c] = make_float2(acc[i][j][2], acc[i][j][3]);
            }
        }
    }
}

// ---------------------------------------------------------------------------
// Registerized softmax: the whole 2048-float row lives in block registers.
// ONE gmem read pass, ONE exp per element (fp32 exp2), ONE fp16 write pass.
// Precision identical to the two-pass version.
// ---------------------------------------------------------------------------
__global__ __launch_bounds__(256) void softmax_kernel(
    const float* __restrict__ S, __half* __restrict__ P)
{
    __shared__ float redm[8], reds[8];
    const int r = blockIdx.x;
    const int qi = r & (SEQ - 1);
    const float* row = S + (size_t)r * SEQ;
    __half* prow = P + (size_t)r * SEQ;
    const int L = qi + 1;
    const int L4 = L >> 2;                 // full float4 count (<= 512)
    const int tid = threadIdx.x;
    const int wid = tid >> 5, lane = tid & 31;

    // Load row into registers: <=2 float4 + <=1 scalar tail per thread.
    const bool h0 = tid < L4;
    const bool h1 = tid + 256 < L4;
    const int ti = L4 * 4 + tid;
    const bool ht = ti < L;
    float4 v0, v1;
    float vt = 0.0f;
    if (h0) v0 = ((const float4*)row)[tid];
    if (h1) v1 = ((const float4*)row)[tid + 256];
    if (ht) vt = row[ti];

    // Block max.
    float m = -FLT_MAX;
    if (h0) m = fmaxf(fmaxf(v0.x, v0.y), fmaxf(v0.z, v0.w));
    if (h1) m = fmaxf(m, fmaxf(fmaxf(v1.x, v1.y), fmaxf(v1.z, v1.w)));
    if (ht) m = fmaxf(m, vt);
    #pragma unroll
    for (int o = 16; o; o >>= 1) m = fmaxf(m, __shfl_xor_sync(0xffffffffu, m, o));
    if (lane == 0) redm[wid] = m;
    __syncthreads();
    float M = -FLT_MAX;
    #pragma unroll
    for (int w = 0; w < 8; ++w) M = fmaxf(M, redm[w]);

    // Exponentials (once) + block sum.
    const float c2 = 1.4426950408889634f;   // log2(e)
    float s = 0.0f;
    float4 e0, e1;
    float et = 0.0f;
    if (h0) {
        e0.x = exp2f((v0.x - M) * c2); e0.y = exp2f((v0.y - M) * c2);
        e0.z = exp2f((v0.z - M) * c2); e0.w = exp2f((v0.w - M) * c2);
        s += e0.x + e0.y + e0.z + e0.w;
    }
    if (h1) {
        e1.x = exp2f((v1.x - M) * c2); e1.y = exp2f((v1.y - M) * c2);
        e1.z = exp2f((v1.z - M) * c2); e1.w = exp2f((v1.w - M) * c2);
        s += e1.x + e1.y + e1.z + e1.w;
    }
    if (ht) {
        et = exp2f((vt - M) * c2);
        s += et;
    }
    #pragma unroll
    for (int o = 16; o; o >>= 1) s += __shfl_xor_sync(0xffffffffu, s, o);
    if (lane == 0) reds[wid] = s;
    __syncthreads();
    float Stot = 0.0f;
    #pragma unroll
    for (int w = 0; w < 8; ++w) Stot += reds[w];
    const float inv = 1.0f / Stot;

    // Scale + fp16 store.
    if (h0) {
        __half2 a = __float22half2_rn(make_float2(e0.x * inv, e0.y * inv));
        __half2 b = __float22half2_rn(make_float2(e0.z * inv, e0.w * inv));
        uint2 o; o.x = *(unsigned*)&a; o.y = *(unsigned*)&b;
        ((uint2*)prow)[tid] = o;
    }
    if (h1) {
        __half2 a = __float22half2_rn(make_float2(e1.x * inv, e1.y * inv));
        __half2 b = __float22half2_rn(make_float2(e1.z * inv, e1.w * inv));
        uint2 o; o.x = *(unsigned*)&a; o.y = *(unsigned*)&b;
        ((uint2*)prow)[tid + 256] = o;
    }
    if (ht) prow[ti] = __float2half_rn(et * inv);

    // Zero the masked tail up to the 128-boundary PV reads.
    const int zEnd = (qi & ~127) + 128;
    for (int j = L + tid; j < zEnd; j += 256) prow[j] = __float2half_rn(0.0f);
}

// ---------------------------------------------------------------------------
extern "C" void kernel_launch(void* const* d_in, const int* in_sizes, int n_in,
                              void* d_out, int out_size)
{
    (void)in_sizes; (void)n_in; (void)out_size;
    const float* x  = (const float*)d_in[0];
    const float* Wq = (const float*)d_in[1];
    const float* bq = (const float*)d_in[2];
    const float* Wk = (const float*)d_in[3];
    const float* bk = (const float*)d_in[4];
    const float* Wv = (const float*)d_in[5];
    const float* bv = (const float*)d_in[6];
    float* out = (float*)d_out;

    __half *xh, *wq, *wk, *wv, *qh, *kh, *vt, *p;
    float *s;
    cudaGetSymbolAddress((void**)&xh, g_xh);
    cudaGetSymbolAddress((void**)&wq, g_wq);
    cudaGetSymbolAddress((void**)&wk, g_wk);
    cudaGetSymbolAddress((void**)&wv, g_wv);
    cudaGetSymbolAddress((void**)&qh, g_qh);
    cudaGetSymbolAddress((void**)&kh, g_kh);
    cudaGetSymbolAddress((void**)&vt, g_vt);
    cudaGetSymbolAddress((void**)&p,  g_p);
    cudaGetSymbolAddress((void**)&s,  g_s);

    cudaFuncSetAttribute(mm_qkv,  cudaFuncAttributeMaxDynamicSharedMemorySize, SMEM_BYTES);
    cudaFuncSetAttribute(mm_h<1>, cudaFuncAttributeMaxDynamicSharedMemorySize, SMEM_BYTES);
    cudaFuncSetAttribute(mm_h<2>, cudaFuncAttributeMaxDynamicSharedMemorySize, SMEM_BYTES);

    dim3 blk(THREADS);

    // Merged operand conversion (x + 3 weight matrices), one launch.
    const int nAll = NX8 + 3 * NW8;
    cvt_all<<<(nAll + 255) / 256, 256>>>(x, Wq, Wk, Wv, xh, wq, wk, wv);

    // Merged QKV projections (V written transposed): (8, 64, 3) = 1536 CTAs
    dim3 gProj(DM / BN, ROWS / BM, 3);
    mm_qkv<<<gProj, blk, SMEM_BYTES>>>(xh, wq, wk, wv, bq, bk, bv, qh, kh, vt);

    // Causal scores (fp32 out)
    dim3 gScores(SEQ / BN, SEQ / BM, BATCH);     // (16, 16, 4)
    mm_h<1><<<gScores, blk, SMEM_BYTES>>>(qh, kh, s);

    // Registerized row softmax (fp32 -> fp16 probs)
    softmax_kernel<<<ROWS, 256>>>(s, p);

    // O = P Vt^T (fp32 out), longest CTAs first
    dim3 gPV(DM / BN, SEQ / BM, BATCH);          // (8, 16, 4)
    mm_h<2><<<gPV, blk, SMEM_BYTES>>>(p, vt, out);
}